// round 10
// baseline (speedup 1.0000x reference)
#include <cuda_runtime.h>
#include <math.h>
#include <stdint.h>

// Problem constants
#define BB 128      // batch
#define TT 128      // time steps
#define FF 128      // features
#define DD 512      // hidden
#define NG 2048     // 4*D
#define KC 64       // K-chunk (elements)
#define NSTAGE 3
#define NBLOCKS 128
#define NTHREADS 256

// block tile: M=64 (2 M-halves) x N=32 (64 N-groups) -> grid 128
#define BM 64
#define BN 32

// padded strides (floats); 68 mod 32 = 4 -> conflict-free fragment LDS
#define ALD 68
#define BLD 68
#define A_ST (BM*ALD)                           // 4352 floats
#define B_ST (BN*BLD)                           // 2176 floats
#define STAGE_FLOATS (A_ST + B_ST)              // 6528
#define SMEM_BYTES (NSTAGE*STAGE_FLOATS*4)      // 78336
#define ZLD 34

// ---- scratch (device globals; no allocation allowed) ----
__device__ float g_h [BB*DD];
__device__ float g_c [BB*DD];
__device__ float g_h0[BB*DD];
__device__ float g_c0[BB*DD];
__device__ float g_hA[BB*DD];
__device__ float g_cA[BB*DD];
__device__ float g_hB[BB*DD];
__device__ float g_cB[BB*DD];
// permuted+tf32-rounded weights: [n][k], n = d*4+gate
__device__ float g_pEW0[NG*FF];
__device__ float g_pEU0[NG*DD];
__device__ float g_pW1s[NG*DD];
__device__ float g_pDW0[NG*FF];
__device__ float g_pDU0[NG*DD];
__device__ float g_pDW1[NG*DD];
__device__ float g_pDU1[NG*DD];
// permuted biases
__device__ float g_pbE0[NG];
__device__ float g_pbE1[NG];
__device__ float g_pbD0[NG];
__device__ float g_pbD1[NG];
// tf32-rounded inputs / feedback
__device__ float g_encR[BB*TT*FF];
__device__ float g_x0R [BB*FF];
__device__ float g_xfb [BB*FF];
// grid barrier state on SEPARATE cache lines
__device__ __align__(128) unsigned g_cnt;
__device__ __align__(128) unsigned g_sns;

// ---- helpers ----
__device__ __forceinline__ float sigmoidf_(float x) { return 1.0f / (1.0f + expf(-x)); }

__device__ __forceinline__ float rna_tf32(float x) {
    unsigned u;
    asm("cvt.rna.tf32.f32 %0, %1;" : "=r"(u) : "f"(x));
    return __uint_as_float(u);
}

__device__ __forceinline__ unsigned smem_u32(const void* p) {
    return (unsigned)__cvta_generic_to_shared(p);
}

#define CP_ASYNC16(dst_u32, src_ptr) \
    asm volatile("cp.async.cg.shared.global [%0], [%1], 16;\n" :: "r"(dst_u32), "l"(src_ptr))
#define CP_COMMIT() asm volatile("cp.async.commit_group;\n" ::: "memory")
#define CP_WAIT1()  asm volatile("cp.async.wait_group 1;\n" ::: "memory")

__device__ __forceinline__ void mma_tf32(float* d,
    unsigned a0, unsigned a1, unsigned a2, unsigned a3, unsigned b0, unsigned b1)
{
    asm volatile(
        "mma.sync.aligned.m16n8k8.row.col.f32.tf32.tf32.f32 "
        "{%0,%1,%2,%3}, {%4,%5,%6,%7}, {%8,%9}, {%0,%1,%2,%3};"
        : "+f"(d[0]), "+f"(d[1]), "+f"(d[2]), "+f"(d[3])
        : "r"(a0), "r"(a1), "r"(a2), "r"(a3), "r"(b0), "r"(b1));
}

// sense-reversal grid barrier; count/sense on separate L2 lines
__device__ __forceinline__ void grid_bar(unsigned& sense)
{
    __threadfence();               // all threads: make prior STG visible gpu-wide
    __syncthreads();
    sense ^= 1u;
    if (threadIdx.x == 0) {
        if (atomicAdd(&g_cnt, 1u) == NBLOCKS - 1) {
            g_cnt = 0;
            __threadfence();
            *(volatile unsigned*)&g_sns = sense;
        } else {
            while (*(volatile unsigned*)&g_sns != sense) __nanosleep(40);
        }
    }
    __syncthreads();
}

// ---- staging primitives (one KC=64 chunk = A:64x256B, B:32x256B) ----
__device__ __forceinline__ void stageA(float* sm, int s, const float* Ap, int lda,
                                       int kA, int mbase, int tid)
{
    const int row = tid >> 2, c0 = (tid & 3) * 4;   // 4 threads/row, 4x16B each
    const float* src = Ap + (size_t)(mbase + row) * lda + kA + c0 * 4;
    const unsigned dst = smem_u32(sm + s * STAGE_FLOATS + row * ALD + c0 * 4);
    #pragma unroll
    for (int j = 0; j < 4; ++j) CP_ASYNC16(dst + j * 16, src + j * 4);
}

__device__ __forceinline__ void stageB(float* sm, int s, const float* Bp, int ldb,
                                       int kB, int nb32, int tid)
{
    const int row = tid >> 3, c0 = (tid & 7) * 2;   // 8 threads/row, 2x16B each
    const float* src = Bp + (size_t)(nb32 + row) * ldb + kB + c0 * 4;
    const unsigned dst = smem_u32(sm + s * STAGE_FLOATS + A_ST + row * BLD + c0 * 4);
    CP_ASYNC16(dst,      src);
    CP_ASYNC16(dst + 16, src + 4);
}

// ================= in-kernel LSTM cell =================
// z[128x2048] = X@BW^T (K1) + H@BU^T (K2) + pbias; gates; hout=rna(o*relu(c2)), cout=c2.
// prestage: 0 = nothing pre-staged; 1 = B chunks 0,1 pre-issued; 2 = A+B chunks 0,1 pre-issued.
__device__ __forceinline__ void run_cell(
    float* sm, int prestage,
    const float* __restrict__ X, int ldx, int K1, const float* __restrict__ BW,
    const float* __restrict__ H, const float* __restrict__ BU, int K2,
    const float* __restrict__ pbias, const float* __restrict__ cin,
    float* __restrict__ hout, float* __restrict__ cout)
{
    const int tid   = threadIdx.x;
    const int lane  = tid & 31;
    const int wid   = tid >> 5;
    const int gid   = lane >> 2;
    const int tidg  = lane & 3;
    const int warpM = wid & 3;
    const int warpN = wid >> 2;
    const int mbase = (blockIdx.x & 1) * BM;
    const int nb    = blockIdx.x >> 1;
    const int nb32  = nb * BN;

    const int nck = (K1 + K2) / KC;

    auto stage = [&](int ck, int s) {
        const int k0 = ck * KC;
        const float* Ap; int lda_, kA; const float* Bp; int kB, ldb;
        if (k0 < K1) { Ap = X; lda_ = ldx; kA = k0;      Bp = BW; kB = k0;      ldb = K1; }
        else         { Ap = H; lda_ = DD;  kA = k0 - K1; Bp = BU; kB = k0 - K1; ldb = K2; }
        stageA(sm, s, Ap, lda_, kA, mbase, tid);
        stageB(sm, s, Bp, ldb,  kB, nb32,  tid);
    };

    // prologue: group0 must contain chunk0, group0+1 must contain chunk1
    if (prestage == 0) {
        stage(0, 0); CP_COMMIT();
        stage(1, 1); CP_COMMIT();
    } else if (prestage == 1) {
        // B0,B1 pre-issued (uncommitted) -> join group0
        stageA(sm, 0, X, ldx, 0,  mbase, tid); CP_COMMIT();
        stageA(sm, 1, X, ldx, KC, mbase, tid); CP_COMMIT();
    } else {
        CP_COMMIT(); CP_COMMIT();   // A+B 0,1 all pre-issued -> group0
    }

    float acc[2][4];
    #pragma unroll
    for (int nt = 0; nt < 2; ++nt)
        #pragma unroll
        for (int e = 0; e < 4; ++e) acc[nt][e] = 0.f;

    for (int ck = 0; ck < nck; ++ck) {
        CP_WAIT1();                 // chunk ck landed (all groups but newest)
        __syncthreads();            // single sync per chunk

        const float* As = sm + (ck % 3) * STAGE_FLOATS;
        const float* Bs = As + A_ST;

        #pragma unroll
        for (int ks = 0; ks < 8; ++ks) {
            const int kb = ks * 8;
            const int rb = warpM * 16;
            unsigned a0 = __float_as_uint(As[(rb + gid    ) * ALD + kb + tidg    ]);
            unsigned a1 = __float_as_uint(As[(rb + gid + 8) * ALD + kb + tidg    ]);
            unsigned a2 = __float_as_uint(As[(rb + gid    ) * ALD + kb + tidg + 4]);
            unsigned a3 = __float_as_uint(As[(rb + gid + 8) * ALD + kb + tidg + 4]);
            #pragma unroll
            for (int nt = 0; nt < 2; ++nt) {
                const int nbase = warpN * 16 + nt * 8;
                unsigned b0 = __float_as_uint(Bs[(nbase + gid) * BLD + kb + tidg    ]);
                unsigned b1 = __float_as_uint(Bs[(nbase + gid) * BLD + kb + tidg + 4]);
                mma_tf32(acc[nt], a0, a1, a2, a3, b0, b1);
            }
        }

        if (ck + 2 < nck) stage(ck + 2, (ck + 2) % 3);
        CP_COMMIT();                // one group per iteration (may be empty)
    }
    __syncthreads();                // all compute done before smem reuse

    // ---- epilogue: fragments -> smem z-tile -> gates ----
    float* zs = sm;
    #pragma unroll
    for (int nt = 0; nt < 2; ++nt) {
        const int row0 = warpM * 16 + gid;
        const int col0 = warpN * 16 + nt * 8 + 2 * tidg;
        zs[(row0    ) * ZLD + col0    ] = acc[nt][0];
        zs[(row0    ) * ZLD + col0 + 1] = acc[nt][1];
        zs[(row0 + 8) * ZLD + col0    ] = acc[nt][2];
        zs[(row0 + 8) * ZLD + col0 + 1] = acc[nt][3];
    }
    __syncthreads();

    {
        const int rl = tid >> 2;
        const int r  = mbase + rl;
        const int db = (tid & 3) * 2;
        #pragma unroll
        for (int d = 0; d < 2; ++d) {
            const int nl  = (db + d) * 4;
            const int col = nb * 8 + db + d;
            float zi = zs[rl * ZLD + nl + 0] + pbias[nb32 + nl + 0];
            float zf = zs[rl * ZLD + nl + 1] + pbias[nb32 + nl + 1];
            float zg = zs[rl * ZLD + nl + 2] + pbias[nb32 + nl + 2];
            float zo = zs[rl * ZLD + nl + 3] + pbias[nb32 + nl + 3];
            float i  = sigmoidf_(zi);
            float f  = sigmoidf_(zf);
            float g  = fmaxf(zg, 0.f);
            float o  = sigmoidf_(zo);
            float c2 = f * cin[r * DD + col] + i * g;
            cout[r * DD + col] = c2;
            hout[r * DD + col] = rna_tf32(o * fmaxf(c2, 0.f));
        }
    }
    __syncthreads();   // zs reads done before caller pre-stages into stage 0/1
}

// ================= persistent megakernel (incl. weight preprocessing) =================
__global__ __launch_bounds__(NTHREADS, 1)
void persist_kernel(const float* __restrict__ eW0, const float* __restrict__ eU0,
                    const float* __restrict__ eb0, const float* __restrict__ eW1,
                    const float* __restrict__ eU1, const float* __restrict__ eb1,
                    const float* __restrict__ dW0, const float* __restrict__ dU0,
                    const float* __restrict__ db0, const float* __restrict__ dW1,
                    const float* __restrict__ dU1, const float* __restrict__ db1,
                    const float* __restrict__ dW,  const float* __restrict__ db_,
                    float* __restrict__ out)
{
    extern __shared__ __align__(16) float sm[];
    const int tid = threadIdx.x;
    unsigned sense = 0;

    const int mbase = (blockIdx.x & 1) * BM;
    const int nb32  = (blockIdx.x >> 1) * BN;

    // ---------------- preprocessing (grid-stride; no smem) ----------------
    {
        const int gt = blockIdx.x * NTHREADS + tid;
        const int NT = NBLOCKS * NTHREADS;
        // K=128 permutes
        for (int i = gt; i < NG * FF; i += NT) {
            int k = i & 127, n = i >> 7, g = n & 3, d = n >> 2;
            size_t si = (size_t)k * NG + g * DD + d;
            g_pEW0[i] = rna_tf32(eW0[si]);
            g_pDW0[i] = rna_tf32(dW0[si]);
        }
        // K=512 permutes (+ fused W1+U1)
        for (int i = gt; i < NG * DD; i += NT) {
            int k = i & 511, n = i >> 9, g = n & 3, d = n >> 2;
            size_t si = (size_t)k * NG + g * DD + d;
            g_pEU0[i] = rna_tf32(eU0[si]);
            g_pW1s[i] = rna_tf32(eW1[si] + eU1[si]);
            g_pDU0[i] = rna_tf32(dU0[si]);
            g_pDW1[i] = rna_tf32(dW1[si]);
            g_pDU1[i] = rna_tf32(dU1[si]);
        }
        for (int n = gt; n < NG; n += NT) {
            int si = (n & 3) * DD + (n >> 2);
            g_pbE0[n] = eb0[si]; g_pbE1[n] = eb1[si];
            g_pbD0[n] = db0[si]; g_pbD1[n] = db1[si];
        }
    }
    grid_bar(sense);

    // ---------------- Encoder: 128 steps, 2 layers ----------------
    for (int t = 0; t < TT; ++t) {
        run_cell(sm, (t == 0) ? 0 : 2,
                 g_encR + (size_t)t * FF, TT * FF, FF, g_pEW0,
                 g_h, g_pEU0, DD, g_pbE0, g_c, g_h0, g_c0);
        // pre-stage layer-1 weights (B only; A = h0 not ready)
        stageB(sm, 0, g_pW1s, DD, 0,  nb32, tid);
        stageB(sm, 1, g_pW1s, DD, KC, nb32, tid);
        grid_bar(sense);

        run_cell(sm, 1, g_h0, DD, DD, g_pW1s,
                 (const float*)nullptr, (const float*)nullptr, 0,
                 g_pbE1, g_c0, g_h, g_c);
        // pre-stage next L0: weights + input (encR / x0R are static -> A safe)
        if (t < TT - 1) {
            stageB(sm, 0, g_pEW0, FF, 0,  nb32, tid);
            stageB(sm, 1, g_pEW0, FF, KC, nb32, tid);
            stageA(sm, 0, g_encR + (size_t)(t + 1) * FF, TT * FF, 0,  mbase, tid);
            stageA(sm, 1, g_encR + (size_t)(t + 1) * FF, TT * FF, KC, mbase, tid);
        } else {
            stageB(sm, 0, g_pDW0, FF, 0,  nb32, tid);
            stageB(sm, 1, g_pDW0, FF, KC, nb32, tid);
            stageA(sm, 0, g_x0R, FF, 0,  mbase, tid);
            stageA(sm, 1, g_x0R, FF, KC, mbase, tid);
        }
        grid_bar(sense);
    }

    // ---------------- Decoder: 128 steps, 2 layers + dense ----------------
    for (int t = 0; t < TT; ++t) {
        const float* hcur = (t == 0) ? g_h : ((t & 1) ? g_hA : g_hB);
        const float* ccur = (t == 0) ? g_c : ((t & 1) ? g_cA : g_cB);
        float* hnext = (t & 1) ? g_hB : g_hA;
        float* cnext = (t & 1) ? g_cB : g_cA;
        const float* X = (t == 0) ? g_x0R : g_xfb;

        // layer 0: reads OLD h,c (reference quirk); its c2 discarded later
        run_cell(sm, (t == 0) ? 2 : 1, X, FF, FF, g_pDW0,
                 hcur, g_pDU0, DD, g_pbD0, ccur, g_h0, g_c0);
        stageB(sm, 0, g_pDW1, DD, 0,  nb32, tid);
        stageB(sm, 1, g_pDW1, DD, KC, nb32, tid);
        grid_bar(sense);

        // layer 1: x = layer0 h, h/c = OLD carry
        run_cell(sm, 1, g_h0, DD, DD, g_pDW1,
                 hcur, g_pDU1, DD, g_pbD1, ccur, hnext, cnext);
        grid_bar(sense);

        // ---- dense: block = batch row; exact fp32 -> out, rounded -> xfb ----
        {
            const int row = blockIdx.x;
            float* hs = sm;            // 512 floats
            float* ps = sm + DD;       // 256 partials
            const float* hrow = hnext + (size_t)row * DD;
            #pragma unroll
            for (int k = tid; k < DD; k += NTHREADS) hs[k] = __ldcg(hrow + k);
            __syncthreads();

            const int col  = tid & 127;
            const int half = tid >> 7;
            const float* wp = dW + (size_t)(half * 256) * FF + col;
            float a0 = 0.f, a1 = 0.f;
            #pragma unroll 8
            for (int k = 0; k < 256; k += 2) {
                a0 += hs[half * 256 + k    ] * wp[(size_t)(k    ) * FF];
                a1 += hs[half * 256 + k + 1] * wp[(size_t)(k + 1) * FF];
            }
            ps[tid] = a0 + a1;
            __syncthreads();
            if (half == 0) {
                float v = ps[col] + ps[128 + col] + db_[col];
                out[((size_t)row * TT + (TT - 1 - t)) * FF + col] = v;
                g_xfb[row * FF + col] = rna_tf32(v);
            }
            __syncthreads();   // ps reads done before pre-staging into stage 0
        }
        // pre-stage next dec L0 weights (A = xfb just written by others -> unsafe)
        if (t < TT - 1) {
            stageB(sm, 0, g_pDW0, FF, 0,  nb32, tid);
            stageB(sm, 1, g_pDW0, FF, KC, nb32, tid);
        }
        grid_bar(sense);
    }
}

// ================= host-side prep kernels (launch indices 0..4) =================
__global__ void zero_kernel(float* p, int n) {
    int i = blockIdx.x * blockDim.x + threadIdx.x;
    if (i < n) p[i] = 0.f;
}
__global__ void zero_bar_kernel() {
    if (threadIdx.x == 0) { g_cnt = 0; g_sns = 0; }
}
__global__ void round_copy_kernel(const float* __restrict__ s, float* __restrict__ d, int n) {
    int i = blockIdx.x * blockDim.x + threadIdx.x;
    if (i < n) d[i] = rna_tf32(s[i]);
}
__global__ void round_slice0_kernel(const float* __restrict__ dec_in, float* __restrict__ d) {
    int i = blockIdx.x * blockDim.x + threadIdx.x;
    if (i < BB * FF) {
        int b = i >> 7, f = i & 127;
        d[i] = rna_tf32(dec_in[(size_t)b * TT * FF + f]);
    }
}

extern "C" void kernel_launch(void* const* d_in, const int* in_sizes, int n_in,
                              void* d_out, int out_size)
{
    const float* enc_in  = (const float*)d_in[0];
    const float* dec_in  = (const float*)d_in[1];
    const float* enc_W0  = (const float*)d_in[2];
    const float* enc_U0  = (const float*)d_in[3];
    const float* enc_b0  = (const float*)d_in[4];
    const float* enc_W1  = (const float*)d_in[5];
    const float* enc_U1  = (const float*)d_in[6];
    const float* enc_b1  = (const float*)d_in[7];
    const float* dec_W0  = (const float*)d_in[8];
    const float* dec_U0  = (const float*)d_in[9];
    const float* dec_b0  = (const float*)d_in[10];
    const float* dec_W1  = (const float*)d_in[11];
    const float* dec_U1  = (const float*)d_in[12];
    const float* dec_b1  = (const float*)d_in[13];
    const float* dense_W = (const float*)d_in[14];
    const float* dense_b = (const float*)d_in[15];
    float* out = (float*)d_out;

    cudaFuncSetAttribute(persist_kernel, cudaFuncAttributeMaxDynamicSharedMemorySize, SMEM_BYTES);

    float *h, *c, *encR, *x0R;
    cudaGetSymbolAddress((void**)&h,    g_h);
    cudaGetSymbolAddress((void**)&c,    g_c);
    cudaGetSymbolAddress((void**)&encR, g_encR);
    cudaGetSymbolAddress((void**)&x0R,  g_x0R);

    // launches 0..4 (persist is launch #5 -> ncu -s 5 captures it)
    zero_kernel<<<(BB * DD + 255) / 256, 256>>>(h, BB * DD);
    zero_kernel<<<(BB * DD + 255) / 256, 256>>>(c, BB * DD);
    zero_bar_kernel<<<1, 32>>>();
    { int n = BB * TT * FF; round_copy_kernel<<<(n + 255) / 256, 256>>>(enc_in, encR, n); }
    round_slice0_kernel<<<(BB * FF + 255) / 256, 256>>>(dec_in, x0R);

    // the whole model in one persistent kernel
    persist_kernel<<<NBLOCKS, NTHREADS, SMEM_BYTES>>>(
        enc_W0, enc_U0, enc_b0, enc_W1, enc_U1, enc_b1,
        dec_W0, dec_U0, dec_b0, dec_W1, dec_U1, dec_b1,
        dense_W, dense_b, out);
}